// round 17
// baseline (speedup 1.0000x reference)
#include <cuda_runtime.h>
#include <math.h>

#define NEG_INF (-1e10f)
#define BATCH 4
#define NN 1024
#define DD 32
#define WPR 32   // u32 words per bitset row
#define FULL 0xFFFFFFFFu
#define NB   256                 // blocks; 2/SM -> 296 slots >= 256 co-resident

// 512KB bitset scratch + 16KB group-max scratch (device globals: allowed)
__device__ unsigned g_bits[BATCH * NN * WPR];
__device__ float    g_gm[BATCH * 32 * DD];   // [b][group][d]
__device__ unsigned g_arrive;                 // monotonic grid-barrier counter

// ---------------------------------------------------------------------------
// ONE persistent kernel, 256 blocks, all co-resident -> grid barrier safe.
// Phase 1 (pack): ONE THREAD = ONE OUTPUT WORD, zero shfls. Thread loads its
//   own contiguous 128B of the edge row (8 x LDG.128, independent -> full
//   MLP), builds the 32-bit mask with pure ALU, one coalesced STG. 2 tasks
//   per thread. Blocks 0..15: warp 'idx' also computes group maxes.
// Barrier: monotonic-counter (epoch = t/NB), graph-replay safe.
// Phase 2 (pool): per block 16 rows (2/warp); round 0 from smem-staged rows
//   0..31; saturated fast path = 1 LDS; exact global fallbacks otherwise.
// ---------------------------------------------------------------------------
__global__ __launch_bounds__(256, 2)
void fused_kernel(const int* __restrict__ edges,
                  const float* __restrict__ feat,
                  float* __restrict__ out) {
    __shared__ unsigned sbits[32 * WPR];   // 4KB: bitset rows 0..31 (phase 2)
    __shared__ float    sbmax[32];         // batch max over group maxes

    const int tid  = threadIdx.x;
    const int lane = tid & 31;
    const int warp = tid >> 5;

    // ===================== Phase 1: pack (shfl-free) =====================
    #pragma unroll
    for (int half = 0; half < 2; ++half) {
        const int task = blockIdx.x * 512 + half * 256 + tid; // (row<<5)|word
        const int row  = task >> 5;
        const int word = task & 31;
        // This thread's 128B slice: columns word*32 .. word*32+31 of row.
        const uint4* src = (const uint4*)(edges + ((size_t)row << 10)) + (word << 3);
        uint4 v[8];
        #pragma unroll
        for (int j = 0; j < 8; ++j) v[j] = src[j];     // 8 independent LDG.128

        unsigned wbits = 0u;
        #pragma unroll
        for (int j = 0; j < 8; ++j) {
            wbits |= ((unsigned)(v[j].x != 0)      ) << (4 * j);
            wbits |= ((unsigned)(v[j].y != 0) << 1u) << (4 * j);
            wbits |= ((unsigned)(v[j].z != 0) << 2u) << (4 * j);
            wbits |= ((unsigned)(v[j].w != 0) << 3u) << (4 * j);
        }
        g_bits[task] = wbits;                          // coalesced 128B/warp
    }

    // group maxes: 128 warp-tasks on blocks 0..15
    if (blockIdx.x < 16) {
        const int idx = blockIdx.x * 8 + warp;         // b*32+g in [0,128)
        const float* f = feat + (size_t)idx * 32 * DD + lane;
        float m0 = f[0], m1 = f[DD], m2 = f[2 * DD], m3 = f[3 * DD];
        #pragma unroll
        for (int j = 4; j < 32; j += 4) {
            m0 = fmaxf(m0, f[j * DD]);
            m1 = fmaxf(m1, f[(j + 1) * DD]);
            m2 = fmaxf(m2, f[(j + 2) * DD]);
            m3 = fmaxf(m3, f[(j + 3) * DD]);
        }
        g_gm[idx * DD + lane] = fmaxf(fmaxf(m0, m1), fmaxf(m2, m3));
    }

    // ===================== Device-wide barrier =====================
    __syncthreads();
    if (tid == 0) {
        __threadfence();                                    // release
        const unsigned t = atomicAdd(&g_arrive, 1u);
        const unsigned target = (t / NB + 1u) * NB;         // epoch end
        while (*(volatile unsigned*)&g_arrive < target) { } // spin
        __threadfence();                                    // acquire
    }
    __syncthreads();

    // ===================== Phase 2: pool (16 rows/block) =====================
    const int b     = blockIdx.x >> 6;                 // batch
    const int ibase = (blockIdx.x & 63) * 16;          // first row of block

    const unsigned* __restrict__ bb = g_bits + (size_t)b * NN * WPR;
    const float*    __restrict__ gm = g_gm + b * 32 * DD;
    const float*    __restrict__ fb = feat + (size_t)b * NN * DD;

    ((uint4*)sbits)[tid] = ((const uint4*)bb)[tid];         // rows 0..31 (4KB)
    if (warp == 0) {
        float m0 = gm[lane],      m1 = gm[32 + lane];
        float m2 = gm[64 + lane], m3 = gm[96 + lane];
        #pragma unroll
        for (int g = 4; g < 32; g += 4) {
            m0 = fmaxf(m0, gm[(g    ) * 32 + lane]);
            m1 = fmaxf(m1, gm[(g + 1) * 32 + lane]);
            m2 = fmaxf(m2, gm[(g + 2) * 32 + lane]);
            m3 = fmaxf(m3, gm[(g + 3) * 32 + lane]);
        }
        sbmax[lane] = fmaxf(fmaxf(m0, m1), fmaxf(m2, m3));
    }
    __syncthreads();

    #pragma unroll 1
    for (int r = 0; r < 2; ++r) {
        const int i = ibase + warp * 2 + r;            // output row
        const unsigned rw = bb[i * WPR + lane];        // row i of E

        // --- round 0 (word 0) from smem ---
        unsigned acc;
        bool sat;
        {
            const unsigned m = __shfl_sync(FULL, rw, 0);    // warp-uniform
            unsigned v0 = 0u, v1 = 0u, v2 = 0u, v3 = 0u;
            #pragma unroll
            for (int t = 0; t < 32; t += 4) {
                v0 |= sbits[((t    ) << 5) + lane] & (unsigned)((int)(m << (31 - t    )) >> 31);
                v1 |= sbits[((t + 1) << 5) + lane] & (unsigned)((int)(m << (31 - t - 1)) >> 31);
                v2 |= sbits[((t + 2) << 5) + lane] & (unsigned)((int)(m << (31 - t - 2)) >> 31);
                v3 |= sbits[((t + 3) << 5) + lane] & (unsigned)((int)(m << (31 - t - 3)) >> 31);
            }
            acc = (v0 | v1) | (v2 | v3);
            sat = __all_sync(FULL, acc == FULL);
        }

        if (sat) {
            out[((size_t)b * NN + i) * DD + lane] = sbmax[lane];
            continue;
        }

        // --- rare rounds w>=1 from global (exact) ---
        #pragma unroll 1
        for (int w = 1; w < 32 && !sat; ++w) {
            const unsigned m = __shfl_sync(FULL, rw, w);
            if (!m) continue;
            const unsigned* __restrict__ gp = bb + ((size_t)w << 10) + lane;
            unsigned v0 = 0u, v1 = 0u, v2 = 0u, v3 = 0u;
            #pragma unroll
            for (int t = 0; t < 32; t += 4) {
                v0 |= gp[(t    ) << 5] & (unsigned)((int)(m << (31 - t    )) >> 31);
                v1 |= gp[(t + 1) << 5] & (unsigned)((int)(m << (31 - t - 1)) >> 31);
                v2 |= gp[(t + 2) << 5] & (unsigned)((int)(m << (31 - t - 2)) >> 31);
                v3 |= gp[(t + 3) << 5] & (unsigned)((int)(m << (31 - t - 3)) >> 31);
            }
            acc |= (v0 | v1) | (v2 | v3);
            sat = __all_sync(FULL, acc == FULL);
        }

        float best;
        if (sat) {
            best = sbmax[lane];
        } else {
            best = -INFINITY;
            #pragma unroll 1
            for (int g = 0; g < 32; ++g) {
                const unsigned mg = __shfl_sync(FULL, acc, g);   // uniform
                const float gmv = gm[(g << 5) + lane];           // L2
                float v;
                if (mg == FULL) {
                    v = gmv;                        // whole group visible
                } else if (mg == 0u) {
                    v = gmv + NEG_INF;              // whole group masked (exact)
                } else {
                    v = -INFINITY;                  // mixed group: per-element
                    for (int jj = 0; jj < 32; ++jj) {
                        float fv = fb[(size_t)((g << 5) + jj) * DD + lane];
                        v = fmaxf(v, fv + (((mg >> jj) & 1u) ? 0.0f : NEG_INF));
                    }
                }
                best = fmaxf(best, v);
            }
        }
        out[((size_t)b * NN + i) * DD + lane] = best;   // coalesced
    }
}

// ---------------------------------------------------------------------------
extern "C" void kernel_launch(void* const* d_in, const int* in_sizes, int n_in,
                              void* d_out, int out_size) {
    const float* feat;
    const int*   edges;
    if (in_sizes[0] == BATCH * NN * DD) {
        feat  = (const float*)d_in[0];
        edges = (const int*)d_in[1];
    } else {
        feat  = (const float*)d_in[1];
        edges = (const int*)d_in[0];
    }

    fused_kernel<<<NB, 256>>>(edges, feat, (float*)d_out);

    (void)n_in; (void)out_size;
}